// round 16
// baseline (speedup 1.0000x reference)
#include <cuda_runtime.h>
#include <cuda_fp16.h>
#include <cstdint>

#define N_NODES 100000
#define E_EDGES 1600000
#define IN_FEAT 256
#define OUT_FEAT 128

#define SCHUNK 256
#define NBLK ((N_NODES + SCHUNK - 1) / SCHUNK)   // 391

// ----- static device scratch (no allocations allowed) -----
__device__ __half   g_supp_h[(size_t)N_NODES * OUT_FEAT];  // 25.6 MB
__device__ uint32_t g_bfrag[32 * 16 * 32 * 2];             // 128 KB, frag-ordered W
__device__ int      g_deg[N_NODES];                        // zero-init at load
__device__ int      g_off[N_NODES + 1];
__device__ int      g_cursor[N_NODES];
__device__ int      g_bsum[NBLK];
__device__ int      g_boff[NBLK];
__device__ int2     g_edge[E_EDGES];                       // (col, weight-bits)

__device__ __forceinline__ uint32_t f2tf32(float f) {
    uint32_t u;
    asm("cvt.rna.tf32.f32 %0, %1;" : "=r"(u) : "f"(f));
    return u;
}

// ---------------------------------------------------------------------------
// Pre-pack W into mma-fragment order:
// g_bfrag[((kt*16 + nt)*32 + lane)*2 + reg],  kt=K/8 tile, nt=N/8 tile
// ---------------------------------------------------------------------------
__global__ __launch_bounds__(256) void prep_b_kernel(const float* __restrict__ w)
{
    int f = blockIdx.x * blockDim.x + threadIdx.x;   // 0..8191 float4s
    if (f >= (IN_FEAT * OUT_FEAT) / 4) return;
    int k = f >> 5;
    int n4 = f & 31;
    float4 v = *reinterpret_cast<const float4*>(&w[(size_t)k * OUT_FEAT + n4 * 4]);
    float vv[4] = {v.x, v.y, v.z, v.w};
    int kt = k >> 3, kin = k & 7;
    int lane_k = kin & 3, reg = kin >> 2;
    #pragma unroll
    for (int q = 0; q < 4; q++) {
        int n = n4 * 4 + q;
        int nt = n >> 3, nin = n & 7;
        int l = nin * 4 + lane_k;
        g_bfrag[((kt * 16 + nt) * 32 + l) * 2 + reg] = f2tf32(vv[q]);
    }
}

// ---------------------------------------------------------------------------
// CSR build (proven)
// ---------------------------------------------------------------------------
__global__ __launch_bounds__(256) void hist_kernel(const int* __restrict__ rowi)
{
    int e = blockIdx.x * blockDim.x + threadIdx.x;
    if (e < E_EDGES) atomicAdd(&g_deg[rowi[e]], 1);
}
__global__ __launch_bounds__(SCHUNK) void reduce_kernel()
{
    __shared__ int s[SCHUNK];
    int i = blockIdx.x * SCHUNK + threadIdx.x;
    int v = (i < N_NODES) ? g_deg[i] : 0;
    s[threadIdx.x] = v;
    __syncthreads();
    for (int stride = SCHUNK / 2; stride > 0; stride >>= 1) {
        if (threadIdx.x < stride) s[threadIdx.x] += s[threadIdx.x + stride];
        __syncthreads();
    }
    if (threadIdx.x == 0) g_bsum[blockIdx.x] = s[0];
}
__global__ __launch_bounds__(512) void scan_bsums_kernel()
{
    __shared__ int s[512];
    int t = threadIdx.x;
    int v = (t < NBLK) ? g_bsum[t] : 0;
    s[t] = v;
    __syncthreads();
    for (int d = 1; d < 512; d <<= 1) {
        int add = (t >= d) ? s[t - d] : 0;
        __syncthreads();
        s[t] += add;
        __syncthreads();
    }
    if (t < NBLK) g_boff[t] = s[t] - v;
}
__global__ __launch_bounds__(SCHUNK) void scan_chunk_kernel()
{
    __shared__ int s[SCHUNK];
    int t = threadIdx.x;
    int i = blockIdx.x * SCHUNK + t;
    int d = (i < N_NODES) ? g_deg[i] : 0;
    s[t] = d;
    __syncthreads();
    for (int st = 1; st < SCHUNK; st <<= 1) {
        int add = (t >= st) ? s[t - st] : 0;
        __syncthreads();
        s[t] += add;
        __syncthreads();
    }
    if (i < N_NODES) {
        int off = g_boff[blockIdx.x] + s[t] - d;
        g_off[i] = off;
        g_cursor[i] = off;
        g_deg[i] = 0;                       // re-zero for next replay
        if (i == N_NODES - 1) g_off[N_NODES] = off + d;
    }
}
__global__ __launch_bounds__(256) void place_kernel(
    const int* __restrict__ rowi, const int* __restrict__ coli,
    const float* __restrict__ ew)
{
    int e = blockIdx.x * blockDim.x + threadIdx.x;
    if (e < E_EDGES) {
        int r = rowi[e];
        int p = atomicAdd(&g_cursor[r], 1);
        g_edge[p] = make_int2(coli[e], __float_as_int(ew[e]));
    }
}

// ---------------------------------------------------------------------------
// Half-N GEMM: computes support cols [n_half*64, n_half*64+64).
// CTA 128x64, 8 warps (4 M x 2 N), warp tile 32x32, BK=32 double-buffered.
// ---------------------------------------------------------------------------
#define A_STRIDE 36
#define A_BUF_WORDS (128 * A_STRIDE)           // 4608
#define BH_BUF_WORDS (4 * 8 * 32 * 2)          // 2048 (half-N chunk)
#define OFF_A0 0
#define OFF_A1 A_BUF_WORDS
#define OFF_B0 (2 * A_BUF_WORDS)
#define OFF_B1 (2 * A_BUF_WORDS + BH_BUF_WORDS)
#define GEMM_SMEM_BYTES ((2 * A_BUF_WORDS + 2 * BH_BUF_WORDS) * 4)   // 53248
#define BH_CHUNK_BYTES (BH_BUF_WORDS * 4)      // 8192

__global__ __launch_bounds__(256) void gemm_half_kernel(
    const float* __restrict__ x,
    __half* __restrict__ sup,
    int n_half)
{
    extern __shared__ uint32_t sm[];
    const uint32_t smem_base = (uint32_t)__cvta_generic_to_shared(sm);

    const int tid = threadIdx.x;
    const int lane = tid & 31;
    const int wid = tid >> 5;
    const int warp_m = wid & 3;
    const int warp_n = wid >> 2;
    const int block_row = blockIdx.x * 128;

    const int qrow = lane >> 2;
    const int qcol = lane & 3;

    const int lt = lane >> 3;
    const int lrr = lane & 7;
    const int lm_row0 = warp_m * 32 + (lt & 1) * 8 + lrr;
    const int lm_colw = (lt >> 1) * 4;

    float acc[2][4][4];
    #pragma unroll
    for (int mt = 0; mt < 2; mt++)
        #pragma unroll
        for (int nt = 0; nt < 4; nt++)
            #pragma unroll
            for (int q = 0; q < 4; q++)
                acc[mt][nt][q] = 0.0f;

    float4 pa[4];

    auto ldg_a = [&](int c) {
        #pragma unroll
        for (int j = 0; j < 4; j++) {
            int f = tid + j * 256;
            int row = f >> 3;
            int col4 = f & 7;
            int grow = block_row + row;
            pa[j] = make_float4(0.f, 0.f, 0.f, 0.f);
            if (grow < N_NODES)
                pa[j] = *reinterpret_cast<const float4*>(
                    &x[(size_t)grow * IN_FEAT + c * 32 + col4 * 4]);
        }
    };
    auto sts_a = [&](int buf) {
        uint32_t* As = sm + (buf ? OFF_A1 : OFF_A0);
        #pragma unroll
        for (int j = 0; j < 4; j++) {
            int f = tid + j * 256;
            int row = f >> 3;
            int col4 = f & 7;
            uint4 t;
            t.x = f2tf32(pa[j].x); t.y = f2tf32(pa[j].y);
            t.z = f2tf32(pa[j].z); t.w = f2tf32(pa[j].w);
            *reinterpret_cast<uint4*>(&As[row * A_STRIDE + col4 * 4]) = t;
        }
    };
    // half-N B chunk: 4 kt-segments of 2048B each, contiguous within segment
    auto cpasync_b = [&](int c, int buf) {
        #pragma unroll
        for (int t = 0; t < 2; t++) {
            int i = tid + t * 256;             // 0..511 (16B units)
            int seg = i >> 7;                  // kt 0..3
            int off_in = i & 127;              // 16B offset in segment
            int kt_g = c * 4 + seg;
            const char* src = reinterpret_cast<const char*>(g_bfrag)
                            + (size_t)(kt_g * 16 + n_half * 8) * 256 + off_in * 16;
            uint32_t dst = smem_base + ((buf ? OFF_B1 : OFF_B0) * 4)
                         + seg * 2048 + off_in * 16;
            asm volatile("cp.async.cg.shared.global [%0], [%1], 16;"
                         :: "r"(dst), "l"(src));
        }
        asm volatile("cp.async.commit_group;" ::: "memory");
    };

    ldg_a(0);
    cpasync_b(0, 0);
    sts_a(0);
    asm volatile("cp.async.wait_group 0;" ::: "memory");
    __syncthreads();

    for (int c = 0; c < 8; c++) {
        if (c + 1 < 8) {
            ldg_a(c + 1);
            cpasync_b(c + 1, (c + 1) & 1);
        }

        const int buf = c & 1;
        const uint32_t a_lm_base = smem_base + ((buf ? OFF_A1 : OFF_A0)
                                 + lm_row0 * A_STRIDE + lm_colw) * 4;
        const uint32_t* Bs = sm + (buf ? OFF_B1 : OFF_B0);

        #pragma unroll
        for (int kt = 0; kt < 4; kt++) {
            uint32_t a[2][4];
            #pragma unroll
            for (int mt = 0; mt < 2; mt++) {
                uint32_t addr = a_lm_base + (mt * 16 * A_STRIDE + kt * 8) * 4;
                asm volatile("ldmatrix.sync.aligned.m8n8.x4.shared.b16 "
                             "{%0,%1,%2,%3}, [%4];"
                             : "=r"(a[mt][0]), "=r"(a[mt][1]),
                               "=r"(a[mt][2]), "=r"(a[mt][3])
                             : "r"(addr));
            }
            const uint32_t* bbase = &Bs[((kt * 8 + warp_n * 4) * 32 + lane) * 2];
            #pragma unroll
            for (int nt = 0; nt < 4; nt++) {
                uint2 bb = *reinterpret_cast<const uint2*>(bbase + nt * 64);
                #pragma unroll
                for (int mt = 0; mt < 2; mt++) {
                    asm("mma.sync.aligned.m16n8k8.row.col.f32.tf32.tf32.f32 "
                        "{%0,%1,%2,%3}, {%4,%5,%6,%7}, {%8,%9}, {%0,%1,%2,%3};"
                        : "+f"(acc[mt][nt][0]), "+f"(acc[mt][nt][1]),
                          "+f"(acc[mt][nt][2]), "+f"(acc[mt][nt][3])
                        : "r"(a[mt][0]), "r"(a[mt][1]), "r"(a[mt][2]), "r"(a[mt][3]),
                          "r"(bb.x), "r"(bb.y));
                }
            }
        }

        if (c + 1 < 8) {
            __syncthreads();
            sts_a((c + 1) & 1);
            asm volatile("cp.async.wait_group 0;" ::: "memory");
            __syncthreads();
        }
    }

    // epilogue: cols n_half*64 + warp_n*32 + nt*8 + qcol*2
    const int rb = block_row + warp_m * 32;
    const int cb = n_half * 64 + warp_n * 32;
    #pragma unroll
    for (int mt = 0; mt < 2; mt++) {
        int r0 = rb + mt * 16 + qrow;
        int r1 = r0 + 8;
        #pragma unroll
        for (int nt = 0; nt < 4; nt++) {
            int col = cb + nt * 8 + qcol * 2;
            if (r0 < N_NODES)
                *reinterpret_cast<__half2*>(&sup[(size_t)r0 * OUT_FEAT + col]) =
                    __floats2half2_rn(acc[mt][nt][0], acc[mt][nt][1]);
            if (r1 < N_NODES)
                *reinterpret_cast<__half2*>(&sup[(size_t)r1 * OUT_FEAT + col]) =
                    __floats2half2_rn(acc[mt][nt][2], acc[mt][nt][3]);
        }
    }
}

// ---------------------------------------------------------------------------
// Half-feature gather: warp per node, lane owns 2 features of the half.
// out[n][h*64 + lane*2 .. +1] = bias + sum_e w_e * supp[col_e][...]
// ---------------------------------------------------------------------------
__global__ __launch_bounds__(256) void gather_half_kernel(
    const float* __restrict__ bias,
    float* __restrict__ out,
    int h)
{
    int gtid = blockIdx.x * blockDim.x + threadIdx.x;
    int n = gtid >> 5;
    int lane = gtid & 31;
    if (n >= N_NODES) return;

    int o0 = g_off[n];
    int o1 = g_off[n + 1];

    const int fo = h * 64 + lane * 2;      // feature offset
    float2 acc = *reinterpret_cast<const float2*>(&bias[fo]);

    int e = o0;
    for (; e + 1 < o1; e += 2) {
        int2 e0 = g_edge[e];
        int2 e1 = g_edge[e + 1];
        float w0 = __int_as_float(e0.y);
        float w1 = __int_as_float(e1.y);
        __half2 h0 = *reinterpret_cast<const __half2*>(
            &g_supp_h[(size_t)e0.x * OUT_FEAT + fo]);
        __half2 h1 = *reinterpret_cast<const __half2*>(
            &g_supp_h[(size_t)e1.x * OUT_FEAT + fo]);
        float2 v0 = __half22float2(h0);
        float2 v1 = __half22float2(h1);
        acc.x = fmaf(v0.x, w0, acc.x);
        acc.y = fmaf(v0.y, w0, acc.y);
        acc.x = fmaf(v1.x, w1, acc.x);
        acc.y = fmaf(v1.y, w1, acc.y);
    }
    if (e < o1) {
        int2 e0 = g_edge[e];
        float w0 = __int_as_float(e0.y);
        __half2 h0 = *reinterpret_cast<const __half2*>(
            &g_supp_h[(size_t)e0.x * OUT_FEAT + fo]);
        float2 v0 = __half22float2(h0);
        acc.x = fmaf(v0.x, w0, acc.x);
        acc.y = fmaf(v0.y, w0, acc.y);
    }

    *reinterpret_cast<float2*>(&out[(size_t)n * OUT_FEAT + fo]) = acc;
}

// ---------------------------------------------------------------------------
extern "C" void kernel_launch(void* const* d_in, const int* in_sizes, int n_in,
                              void* d_out, int out_size)
{
    const float* x    = (const float*)d_in[0];
    const float* w    = (const float*)d_in[1];
    const float* bias = (const float*)d_in[2];
    const float* ew   = (const float*)d_in[3];
    const int*   rowi = (const int*)d_in[4];
    const int*   coli = (const int*)d_in[5];
    float* out = (float*)d_out;

    __half* sup;
    cudaGetSymbolAddress((void**)&sup, g_supp_h);

    // one-time host-side setup (first call = un-captured correctness run)
    static cudaStream_t s2 = nullptr;
    static cudaEvent_t evFork = nullptr, evPrep = nullptr,
                       evCsr = nullptr, evG2 = nullptr;
    if (s2 == nullptr) {
        cudaStreamCreateWithFlags(&s2, cudaStreamNonBlocking);
        cudaEventCreateWithFlags(&evFork, cudaEventDisableTiming);
        cudaEventCreateWithFlags(&evPrep, cudaEventDisableTiming);
        cudaEventCreateWithFlags(&evCsr, cudaEventDisableTiming);
        cudaEventCreateWithFlags(&evG2, cudaEventDisableTiming);
        cudaFuncSetAttribute(gemm_half_kernel,
                             cudaFuncAttributeMaxDynamicSharedMemorySize,
                             GEMM_SMEM_BYTES);
    }

    const int gemm_blocks = (N_NODES + 127) / 128;
    const long long gthreads = (long long)N_NODES * 32;
    const int gather_blocks = (int)((gthreads + 255) / 256);

    // fork
    cudaEventRecord(evFork, 0);
    cudaStreamWaitEvent(s2, evFork, 0);

    // s1: prep + gemm half 0                       (kernel idx 0, 3)
    prep_b_kernel<<<32, 256>>>(w);                                       // 0
    cudaEventRecord(evPrep, 0);
    // s2: CSR chain                                (kernel idx 1, 2, 4, 5, 6)
    hist_kernel<<<(E_EDGES + 255) / 256, 256, 0, s2>>>(rowi);            // 1
    reduce_kernel<<<NBLK, SCHUNK, 0, s2>>>();                            // 2
    gemm_half_kernel<<<gemm_blocks, 256, GEMM_SMEM_BYTES>>>(x, sup, 0);  // 3 (ncu slot)
    scan_bsums_kernel<<<1, 512, 0, s2>>>();                              // 4
    scan_chunk_kernel<<<NBLK, SCHUNK, 0, s2>>>();                        // 5
    place_kernel<<<(E_EDGES + 255) / 256, 256, 0, s2>>>(rowi, coli, ew); // 6
    cudaEventRecord(evCsr, s2);

    // s2: gemm half 1 (needs prep; CSR chain precedes it in-stream)
    cudaStreamWaitEvent(s2, evPrep, 0);
    gemm_half_kernel<<<gemm_blocks, 256, GEMM_SMEM_BYTES, s2>>>(x, sup, 1); // 7
    cudaEventRecord(evG2, s2);

    // s1: gather half 0 (needs gemm h0 [in-stream] + CSR)
    cudaStreamWaitEvent(0, evCsr, 0);
    gather_half_kernel<<<gather_blocks, 256>>>(bias, out, 0);            // 8

    // s1: gather half 1 (needs gemm h1)
    cudaStreamWaitEvent(0, evG2, 0);
    gather_half_kernel<<<gather_blocks, 256>>>(bias, out, 1);            // 9
}

// round 17
// speedup vs baseline: 1.5244x; 1.5244x over previous
#include <cuda_runtime.h>
#include <cuda_fp16.h>
#include <cstdint>

#define N_NODES 100000
#define E_EDGES 1600000
#define IN_FEAT 256
#define OUT_FEAT 128

#define SCHUNK 256
#define NBLK ((N_NODES + SCHUNK - 1) / SCHUNK)   // 391

// ----- static device scratch (no allocations allowed) -----
__device__ __half   g_supp_h[(size_t)N_NODES * OUT_FEAT];  // 25.6 MB
__device__ uint32_t g_bfragh[16 * 16 * 32 * 2];            // 64 KB, fp16 frag W
__device__ int      g_deg[N_NODES];                        // zero-init at load
__device__ int      g_off[N_NODES + 1];
__device__ int      g_cursor[N_NODES];
__device__ int      g_bsum[NBLK];
__device__ int      g_boff[NBLK];
__device__ int2     g_edge[E_EDGES];                       // (col, weight-bits)

// ---------------------------------------------------------------------------
// Pre-pack W into m16n8k16 fp16 B-fragment order:
// g_bfragh[((kt16*16 + nt)*32 + lane)*2 + reg] = half2(B[k][n], B[k+1][n])
//   k = kt16*16 + reg*8 + (lane%4)*2,  n = nt*8 + lane/4
// ---------------------------------------------------------------------------
__global__ __launch_bounds__(256) void prep_b_kernel(const float* __restrict__ w)
{
    int idx = blockIdx.x * blockDim.x + threadIdx.x;   // 0..16383
    if (idx >= 16 * 16 * 32 * 2) return;
    int reg  = idx & 1;
    int lane = (idx >> 1) & 31;
    int nt   = (idx >> 6) & 15;
    int kt16 = idx >> 10;
    int k = kt16 * 16 + reg * 8 + (lane & 3) * 2;
    int n = nt * 8 + (lane >> 2);
    float v0 = w[(size_t)k * OUT_FEAT + n];
    float v1 = w[(size_t)(k + 1) * OUT_FEAT + n];
    __half2 h = __floats2half2_rn(v0, v1);
    g_bfragh[idx] = *reinterpret_cast<uint32_t*>(&h);
}

// ---------------------------------------------------------------------------
// CSR build (proven)
// ---------------------------------------------------------------------------
__global__ __launch_bounds__(256) void hist_kernel(const int* __restrict__ rowi)
{
    int e = blockIdx.x * blockDim.x + threadIdx.x;
    if (e < E_EDGES) atomicAdd(&g_deg[rowi[e]], 1);
}
__global__ __launch_bounds__(SCHUNK) void reduce_kernel()
{
    __shared__ int s[SCHUNK];
    int i = blockIdx.x * SCHUNK + threadIdx.x;
    int v = (i < N_NODES) ? g_deg[i] : 0;
    s[threadIdx.x] = v;
    __syncthreads();
    for (int stride = SCHUNK / 2; stride > 0; stride >>= 1) {
        if (threadIdx.x < stride) s[threadIdx.x] += s[threadIdx.x + stride];
        __syncthreads();
    }
    if (threadIdx.x == 0) g_bsum[blockIdx.x] = s[0];
}
__global__ __launch_bounds__(512) void scan_bsums_kernel()
{
    __shared__ int s[512];
    int t = threadIdx.x;
    int v = (t < NBLK) ? g_bsum[t] : 0;
    s[t] = v;
    __syncthreads();
    for (int d = 1; d < 512; d <<= 1) {
        int add = (t >= d) ? s[t - d] : 0;
        __syncthreads();
        s[t] += add;
        __syncthreads();
    }
    if (t < NBLK) g_boff[t] = s[t] - v;
}
__global__ __launch_bounds__(SCHUNK) void scan_chunk_kernel()
{
    __shared__ int s[SCHUNK];
    int t = threadIdx.x;
    int i = blockIdx.x * SCHUNK + t;
    int d = (i < N_NODES) ? g_deg[i] : 0;
    s[t] = d;
    __syncthreads();
    for (int st = 1; st < SCHUNK; st <<= 1) {
        int add = (t >= st) ? s[t - st] : 0;
        __syncthreads();
        s[t] += add;
        __syncthreads();
    }
    if (i < N_NODES) {
        int off = g_boff[blockIdx.x] + s[t] - d;
        g_off[i] = off;
        g_cursor[i] = off;
        g_deg[i] = 0;                       // re-zero for next replay
        if (i == N_NODES - 1) g_off[N_NODES] = off + d;
    }
}
__global__ __launch_bounds__(256) void place_kernel(
    const int* __restrict__ rowi, const int* __restrict__ coli,
    const float* __restrict__ ew)
{
    int e = blockIdx.x * blockDim.x + threadIdx.x;
    if (e < E_EDGES) {
        int r = rowi[e];
        int p = atomicAdd(&g_cursor[r], 1);
        g_edge[p] = make_int2(coli[e], __float_as_int(ew[e]));
    }
}

// ---------------------------------------------------------------------------
// GEMM via mma.sync fp16 m16n8k16 (fp32 accum).
// CTA 128x128, 8 warps (4 M x 2 N), warp tile 32x64, BK=32 double-buffered.
// A in smem as fp16 rows (stride 40 halfs: conflict-free ldmatrix),
// B prepacked fragments streamed by cp.async (8 KB/chunk, contiguous).
// ---------------------------------------------------------------------------
#define A_STRIDE_H 40
#define A_BUF_BYTES (128 * A_STRIDE_H * 2)     // 10240
#define B_CHUNK_BYTES 8192
#define OFF_A0 0
#define OFF_A1 A_BUF_BYTES
#define OFF_B0 (2 * A_BUF_BYTES)               // 20480
#define OFF_B1 (OFF_B0 + B_CHUNK_BYTES)        // 28672
#define GEMM_SMEM_BYTES (OFF_B1 + B_CHUNK_BYTES)  // 36864

__global__ __launch_bounds__(256) void gemm_mma_kernel(
    const float* __restrict__ x,
    __half* __restrict__ sup)
{
    extern __shared__ char smc[];
    const uint32_t smem_base = (uint32_t)__cvta_generic_to_shared(smc);

    const int tid = threadIdx.x;
    const int lane = tid & 31;
    const int wid = tid >> 5;
    const int warp_m = wid & 3;
    const int warp_n = wid >> 2;
    const int block_row = blockIdx.x * 128;

    const int qrow = lane >> 2;
    const int qcol = lane & 3;

    // ldmatrix lane->address mapping (4 tiles of 8x8 b16)
    const int lt = lane >> 3;
    const int lrr = lane & 7;
    const int lm_row0 = warp_m * 32 + (lt & 1) * 8 + lrr;   // + mt*16
    const int lm_colh = (lt >> 1) * 8;                      // + kt16*16 halfs

    float acc[2][8][4];
    #pragma unroll
    for (int mt = 0; mt < 2; mt++)
        #pragma unroll
        for (int nt = 0; nt < 8; nt++)
            #pragma unroll
            for (int q = 0; q < 4; q++)
                acc[mt][nt][q] = 0.0f;

    float4 pa[4];

    // A LDG: 128x32 floats per chunk; f = tid + j*256, row = f>>3, col4 = f&7
    auto ldg_a = [&](int c) {
        #pragma unroll
        for (int j = 0; j < 4; j++) {
            int f = tid + j * 256;
            int row = f >> 3;
            int col4 = f & 7;
            int grow = block_row + row;
            pa[j] = make_float4(0.f, 0.f, 0.f, 0.f);
            if (grow < N_NODES)
                pa[j] = *reinterpret_cast<const float4*>(
                    &x[(size_t)grow * IN_FEAT + c * 32 + col4 * 4]);
        }
    };
    // STS A as fp16: 8 B per j (uint2)
    auto sts_a = [&](int buf) {
        char* As = smc + (buf ? OFF_A1 : OFF_A0);
        #pragma unroll
        for (int j = 0; j < 4; j++) {
            int f = tid + j * 256;
            int row = f >> 3;
            int col4 = f & 7;
            __half2 h0 = __floats2half2_rn(pa[j].x, pa[j].y);
            __half2 h1 = __floats2half2_rn(pa[j].z, pa[j].w);
            uint2 v = make_uint2(*reinterpret_cast<uint32_t*>(&h0),
                                 *reinterpret_cast<uint32_t*>(&h1));
            *reinterpret_cast<uint2*>(As + (row * A_STRIDE_H + col4 * 4) * 2) = v;
        }
    };
    // B chunk: contiguous 8 KB of prepacked fragments
    auto cpasync_b = [&](int c, int buf) {
        uint32_t dst0 = smem_base + (buf ? OFF_B1 : OFF_B0) + tid * 16;
        const char* src0 = reinterpret_cast<const char*>(g_bfragh)
                         + (size_t)c * B_CHUNK_BYTES + tid * 16;
        #pragma unroll
        for (int j = 0; j < 2; j++) {
            asm volatile("cp.async.cg.shared.global [%0], [%1], 16;"
                         :: "r"(dst0 + j * 4096), "l"(src0 + j * 4096));
        }
        asm volatile("cp.async.commit_group;" ::: "memory");
    };

    ldg_a(0);
    cpasync_b(0, 0);
    sts_a(0);
    asm volatile("cp.async.wait_group 0;" ::: "memory");
    __syncthreads();

    for (int c = 0; c < 8; c++) {
        if (c + 1 < 8) {
            ldg_a(c + 1);
            cpasync_b(c + 1, (c + 1) & 1);
        }

        const int buf = c & 1;
        const uint32_t a_lm_base = smem_base + (buf ? OFF_A1 : OFF_A0)
                                 + (lm_row0 * A_STRIDE_H + lm_colh) * 2;
        const uint32_t* Bs = reinterpret_cast<const uint32_t*>(
            smc + (buf ? OFF_B1 : OFF_B0));

        #pragma unroll
        for (int kt16 = 0; kt16 < 2; kt16++) {
            uint32_t a[2][4];
            #pragma unroll
            for (int mt = 0; mt < 2; mt++) {
                uint32_t addr = a_lm_base + (mt * 16 * A_STRIDE_H + kt16 * 16) * 2;
                asm volatile("ldmatrix.sync.aligned.m8n8.x4.shared.b16 "
                             "{%0,%1,%2,%3}, [%4];"
                             : "=r"(a[mt][0]), "=r"(a[mt][1]),
                               "=r"(a[mt][2]), "=r"(a[mt][3])
                             : "r"(addr));
            }
            const uint32_t* bbase = &Bs[((kt16 * 16 + warp_n * 8) * 32 + lane) * 2];
            #pragma unroll
            for (int nt = 0; nt < 8; nt++) {
                uint2 bb = *reinterpret_cast<const uint2*>(bbase + nt * 64);
                #pragma unroll
                for (int mt = 0; mt < 2; mt++) {
                    asm("mma.sync.aligned.m16n8k16.row.col.f32.f16.f16.f32 "
                        "{%0,%1,%2,%3}, {%4,%5,%6,%7}, {%8,%9}, {%0,%1,%2,%3};"
                        : "+f"(acc[mt][nt][0]), "+f"(acc[mt][nt][1]),
                          "+f"(acc[mt][nt][2]), "+f"(acc[mt][nt][3])
                        : "r"(a[mt][0]), "r"(a[mt][1]), "r"(a[mt][2]), "r"(a[mt][3]),
                          "r"(bb.x), "r"(bb.y));
                }
            }
        }

        if (c + 1 < 8) {
            __syncthreads();
            sts_a((c + 1) & 1);
            asm volatile("cp.async.wait_group 0;" ::: "memory");
            __syncthreads();
        }
    }

    // epilogue: fp16 stores
    const int rb = block_row + warp_m * 32;
    #pragma unroll
    for (int mt = 0; mt < 2; mt++) {
        int r0 = rb + mt * 16 + qrow;
        int r1 = r0 + 8;
        #pragma unroll
        for (int nt = 0; nt < 8; nt++) {
            int col = warp_n * 64 + nt * 8 + qcol * 2;
            if (r0 < N_NODES)
                *reinterpret_cast<__half2*>(&sup[(size_t)r0 * OUT_FEAT + col]) =
                    __floats2half2_rn(acc[mt][nt][0], acc[mt][nt][1]);
            if (r1 < N_NODES)
                *reinterpret_cast<__half2*>(&sup[(size_t)r1 * OUT_FEAT + col]) =
                    __floats2half2_rn(acc[mt][nt][2], acc[mt][nt][3]);
        }
    }
}

// ---------------------------------------------------------------------------
// Gather: warp per node, fp16 support rows, packed edges (proven).
// ---------------------------------------------------------------------------
__global__ __launch_bounds__(256) void gather_kernel(
    const float* __restrict__ bias,
    float* __restrict__ out)
{
    int gtid = blockIdx.x * blockDim.x + threadIdx.x;
    int n = gtid >> 5;
    int lane = gtid & 31;
    if (n >= N_NODES) return;

    int o0 = g_off[n];
    int o1 = g_off[n + 1];

    float4 acc = reinterpret_cast<const float4*>(bias)[lane];

    int e = o0;
    for (; e + 1 < o1; e += 2) {
        int2 e0 = g_edge[e];
        int2 e1 = g_edge[e + 1];
        float w0 = __int_as_float(e0.y);
        float w1 = __int_as_float(e1.y);
        uint2 h0 = *reinterpret_cast<const uint2*>(
            &g_supp_h[(size_t)e0.x * OUT_FEAT + lane * 4]);
        uint2 h1 = *reinterpret_cast<const uint2*>(
            &g_supp_h[(size_t)e1.x * OUT_FEAT + lane * 4]);
        float2 a0 = __half22float2(*reinterpret_cast<__half2*>(&h0.x));
        float2 b0 = __half22float2(*reinterpret_cast<__half2*>(&h0.y));
        float2 a1 = __half22float2(*reinterpret_cast<__half2*>(&h1.x));
        float2 b1 = __half22float2(*reinterpret_cast<__half2*>(&h1.y));
        acc.x = fmaf(a0.x, w0, acc.x);
        acc.y = fmaf(a0.y, w0, acc.y);
        acc.z = fmaf(b0.x, w0, acc.z);
        acc.w = fmaf(b0.y, w0, acc.w);
        acc.x = fmaf(a1.x, w1, acc.x);
        acc.y = fmaf(a1.y, w1, acc.y);
        acc.z = fmaf(b1.x, w1, acc.z);
        acc.w = fmaf(b1.y, w1, acc.w);
    }
    if (e < o1) {
        int2 e0 = g_edge[e];
        float w0 = __int_as_float(e0.y);
        uint2 h0 = *reinterpret_cast<const uint2*>(
            &g_supp_h[(size_t)e0.x * OUT_FEAT + lane * 4]);
        float2 a0 = __half22float2(*reinterpret_cast<__half2*>(&h0.x));
        float2 b0 = __half22float2(*reinterpret_cast<__half2*>(&h0.y));
        acc.x = fmaf(a0.x, w0, acc.x);
        acc.y = fmaf(a0.y, w0, acc.y);
        acc.z = fmaf(b0.x, w0, acc.z);
        acc.w = fmaf(b0.y, w0, acc.w);
    }

    reinterpret_cast<float4*>(out + (size_t)n * OUT_FEAT)[lane] = acc;
}

// ---------------------------------------------------------------------------
extern "C" void kernel_launch(void* const* d_in, const int* in_sizes, int n_in,
                              void* d_out, int out_size)
{
    const float* x    = (const float*)d_in[0];
    const float* w    = (const float*)d_in[1];
    const float* bias = (const float*)d_in[2];
    const float* ew   = (const float*)d_in[3];
    const int*   rowi = (const int*)d_in[4];
    const int*   coli = (const int*)d_in[5];
    float* out = (float*)d_out;

    __half* sup;
    cudaGetSymbolAddress((void**)&sup, g_supp_h);

    // one-time host-side setup (first call = un-captured correctness run)
    static cudaStream_t s2 = nullptr;
    static cudaEvent_t evFork = nullptr, evJoin = nullptr;
    if (s2 == nullptr) {
        cudaStreamCreateWithFlags(&s2, cudaStreamNonBlocking);
        cudaEventCreateWithFlags(&evFork, cudaEventDisableTiming);
        cudaEventCreateWithFlags(&evJoin, cudaEventDisableTiming);
        cudaFuncSetAttribute(gemm_mma_kernel,
                             cudaFuncAttributeMaxDynamicSharedMemorySize,
                             GEMM_SMEM_BYTES);
    }

    // fork: s2 joins the capture graph as a parallel branch
    cudaEventRecord(evFork, 0);
    cudaStreamWaitEvent(s2, evFork, 0);

    // default stream: GEMM dataflow              (submission idx 0, 3)
    prep_b_kernel<<<64, 256>>>(w);                                      // 0
    // s2: CSR dataflow                           (submission idx 1, 2, 4, 5, 6)
    hist_kernel<<<(E_EDGES + 255) / 256, 256, 0, s2>>>(rowi);           // 1
    reduce_kernel<<<NBLK, SCHUNK, 0, s2>>>();                           // 2
    gemm_mma_kernel<<<(N_NODES + 127) / 128, 256, GEMM_SMEM_BYTES>>>(   // 3 (ncu slot)
        x, sup);
    scan_bsums_kernel<<<1, 512, 0, s2>>>();                             // 4
    scan_chunk_kernel<<<NBLK, SCHUNK, 0, s2>>>();                       // 5
    place_kernel<<<(E_EDGES + 255) / 256, 256, 0, s2>>>(rowi, coli, ew);// 6

    // join: gather needs both branches
    cudaEventRecord(evJoin, s2);
    cudaStreamWaitEvent(0, evJoin, 0);
    {
        long long threads = (long long)N_NODES * 32;
        int blocks = (int)((threads + 255) / 256);
        gather_kernel<<<blocks, 256>>>(bias, out);                      // 7
    }
}